// round 11
// baseline (speedup 1.0000x reference)
#include <cuda_runtime.h>

// SigNet: depth-4 path signature (C=8 incl. time) + linear head.
// K1: R10-exact scan — 8-way segmented scalar Chen scan + in-smem tree combine.
// K2: split-k GEMM, 296-CTA balanced wave, f32x2 k-pair packed inner loop
//     (both operands naturally k-adjacent; accumulators pair over k-parity).
// K3: reduce + bias.

#define NB      128
#define SLEN    1024
#define NSEG    8
#define SEG     128
#define CIN     7
#define SIGCH   4680          // 8 + 64 + 512 + 4096
#define YSTRIDE 4736          // 37*128; pad [4680,4736) stays zero
#define DOUT    256
#define KSPLIT  37
#define KCHUNK  128           // 37*128 = 4736

typedef unsigned long long u64;
__device__ __forceinline__ u64 fma2(u64 a, u64 b, u64 c){ u64 d; asm("fma.rn.f32x2 %0,%1,%2,%3;" : "=l"(d) : "l"(a),"l"(b),"l"(c)); return d; }
__device__ __forceinline__ float2 unpack2(u64 a){ float2 f; asm("mov.b64 {%0,%1},%2;" : "=f"(f.x),"=f"(f.y) : "l"(a)); return f; }

__device__ float g_y[NB * YSTRIDE];
__device__ float g_part[KSPLIT * NB * DOUT];

// smem: vs[1024][8] = 8192 floats, then reused as T[8][4680] = 37440 floats.
#define SMEM_FLOATS (NSEG * SIGCH)     // 37440 floats = 149760 B

// ---- Chen combine pieces (X = A o B, A earlier in time) ----
__device__ __forceinline__ void chen_l4(const float* __restrict__ A,
                                        const float* __restrict__ B,
                                        float* __restrict__ X, int lane, int nth)
{
    for (int e = lane; e < 4096; e += nth) {
        float v = A[584 + e] + B[584 + e];
        v = fmaf(A[e >> 9],        B[72 + (e & 511)], v);
        v = fmaf(A[8 + (e >> 6)],  B[8  + (e & 63)],  v);
        v = fmaf(A[72 + (e >> 3)], B[e & 7],          v);
        X[584 + e] = v;
    }
}
__device__ __forceinline__ void chen_l3(const float* __restrict__ A,
                                        const float* __restrict__ B,
                                        float* __restrict__ X, int lane, int nth)
{
    for (int e = lane; e < 512; e += nth) {
        float v = A[72 + e] + B[72 + e];
        v = fmaf(A[e >> 6],       B[8 + (e & 63)], v);
        v = fmaf(A[8 + (e >> 3)], B[e & 7],        v);
        X[72 + e] = v;
    }
}
__device__ __forceinline__ void chen_inplace(float* __restrict__ A,
                                             const float* __restrict__ B,
                                             int lane, int nth)
{
    chen_l4(A, B, A, lane, nth);      // reads A[0..584), writes A[584..)
    __syncthreads();
    chen_l3(A, B, A, lane, nth);      // reads A[0..72), writes A[72..584)
    float v2 = 0.0f, v1 = 0.0f;
    if (lane < 64) v2 = A[8 + lane] + B[8 + lane] + A[lane >> 3] * B[lane & 7];
    if (lane < 8)  v1 = A[lane] + B[lane];
    __syncthreads();
    if (lane < 64) A[8 + lane] = v2;
    if (lane < 8)  A[lane] = v1;
}

// ---------------------------------------------------------------------------
// Kernel 1: segmented scan. 1 CTA/batch, 512 threads = 8 groups x 64.
// Thread u=tid&63 owns (a,b)=(u>>3,u&7): all 8 c, all 8 d (64 L4 accumulators).
// ---------------------------------------------------------------------------
__global__ __launch_bounds__(512, 1) void sig_scan_kernel(const float* __restrict__ inp)
{
    extern __shared__ float sm[];
    const int b   = blockIdx.x;
    const int tid = threadIdx.x;

    // Build increments into sm[0..8192). Basepoint 0: first inc = first sample.
    const float dt = 1.0f / 1023.0f;
    const float* x = inp + (size_t)b * SLEN * CIN;
    for (int i = tid; i < SLEN * CIN; i += 512) {
        int t = i / CIN, c = i - t * CIN;
        float cur  = x[i];
        float prev = (t == 0) ? 0.0f : x[i - CIN];
        sm[t * 8 + c + 1] = cur - prev;
    }
    for (int t = tid; t < SLEN; t += 512)
        sm[t * 8] = (t == 0) ? 0.0f : dt;
    __syncthreads();

    const int g  = tid >> 6;          // segment 0..7
    const int u  = tid & 63;          // (a,b)
    const int a  = u >> 3;
    const int bb = u & 7;

    float s1 = 0.0f, s2 = 0.0f;
    float s3[8];
    float sig4[64];
#pragma unroll
    for (int i = 0; i < 8; i++) s3[i] = 0.0f;
#pragma unroll
    for (int i = 0; i < 64; i++) sig4[i] = 0.0f;

    const float inv24 = 1.0f / 24.0f;
    const float inv6  = 1.0f / 6.0f;
    const float* vrow = sm + g * SEG * 8;

#pragma unroll 1
    for (int t = 0; t < SEG; t++) {
        float vv[8];
        *(float4*)&vv[0] = *(const float4*)&vrow[t * 8];
        *(float4*)&vv[4] = *(const float4*)&vrow[t * 8 + 4];
        // Runtime-offset reads come from SHARED (LDS), never from the register
        // array: vv[a] would force vv into local memory.
        float va = vrow[t * 8 + a];
        float vb = vrow[t * 8 + bb];

        // All derived from OLD s1,s2,s3.
        float t6 = fmaf(s1, inv6, va * inv24);   // va/24 + s1/6
        float uu = fmaf(s1, 0.5f, va * inv6);    // va/6  + s1/2
        float m1 = fmaf(vb, t6, s2 * 0.5f);      // vb*t6 + s2/2
        float m2 = fmaf(vb, uu, s2);             // vb*uu + s2

        float K[8];
#pragma unroll
        for (int c = 0; c < 8; c++) {
            K[c]  = fmaf(vv[c], m1, s3[c]);
            s3[c] = fmaf(vv[c], m2, s3[c]);
        }
#pragma unroll
        for (int c = 0; c < 8; c++)
#pragma unroll
            for (int d = 0; d < 8; d++)
                sig4[c * 8 + d] = fmaf(K[c], vv[d], sig4[c * 8 + d]);

        s2 = fmaf(vb, fmaf(va, 0.5f, s1), s2);   // s2 + va*vb/2 + s1*vb
        s1 += va;
    }

    // All scan reads of sm done -> safe to overwrite with T[8][4680].
    __syncthreads();

    // Fully unrolled write-out: every sig4 index is a compile-time constant.
    float* P = sm + g * SIGCH;
#pragma unroll
    for (int c = 0; c < 8; c++) {
#pragma unroll
        for (int d = 0; d < 8; d++)
            P[584 + u * 64 + c * 8 + d] = sig4[c * 8 + d];
        P[72 + u * 8 + c] = s3[c];
    }
    P[8 + u] = s2;
    if (bb == 0) P[a] = s1;
    __syncthreads();

    // Round 1: 4 parallel in-place combines, 128 threads each.
    {
        int pair = tid >> 7, lane = tid & 127;
        float* A = sm + (2 * pair) * SIGCH;
        const float* B = A + SIGCH;
        chen_inplace(A, B, lane, 128);
    }
    __syncthreads();
    // Round 2: 2 parallel in-place combines, 256 threads each.
    {
        int pair = tid >> 8, lane = tid & 255;
        float* A = sm + (4 * pair) * SIGCH;
        const float* B = A + 2 * SIGCH;
        chen_inplace(A, B, lane, 256);
    }
    __syncthreads();
    // Round 3: final combine straight to global.
    {
        const float* A = sm;
        const float* B = sm + 4 * SIGCH;
        float* y = g_y + (size_t)b * YSTRIDE;
        chen_l4(A, B, y, tid, 512);
        chen_l3(A, B, y, tid, 512);
        if (tid < 64) y[8 + tid] = A[8 + tid] + B[8 + tid] + A[tid >> 3] * B[tid & 7];
        if (tid < 8)  y[tid] = A[tid] + B[tid];
        if (tid < YSTRIDE - SIGCH) y[SIGCH + tid] = 0.0f;   // 56 pad elems
    }
}

// ---------------------------------------------------------------------------
// Kernel 2: split-k GEMM partials. grid = (8 col-groups, KSPLIT=37) = 296 CTAs.
// CTA: 128 batch-rows x 32 out-cols over 128 of k. 256 threads.
// f32x2 k-pair packing: accumulators pair over k-parity (summed in epilogue);
// y pairs from ys rows, w pairs from ws[col][k] — both native LDS.64.
// 36-float row pitch: 8B-aligned u64 loads, broadcast-friendly.
// ---------------------------------------------------------------------------
__global__ __launch_bounds__(256, 2) void gemm_part_kernel(const float* __restrict__ W)
{
    __shared__ float ys[128][36];
    __shared__ float ws[32][36];    // [col][k]

    const int tid = threadIdx.x;
    const int cg = blockIdx.x;      // cols cg*32 .. cg*32+31
    const int sp = blockIdx.y;      // k in [sp*128, sp*128+128)
    const int kbase = sp * KCHUNK;

    const int cp = tid & 7;         // cols 4cp .. 4cp+3
    const int rg = tid >> 3;        // rows rg + 32*i, i<4

    u64 acc2[4][4];
#pragma unroll
    for (int i = 0; i < 4; i++)
#pragma unroll
        for (int j = 0; j < 4; j++) acc2[i][j] = 0ull;

    for (int kc = 0; kc < KCHUNK; kc += 32) {
        const int k0 = kbase + kc;
        // y tile: 128 x 32
#pragma unroll
        for (int ii = 0; ii < 4; ii++) {
            int lin = tid + 256 * ii;
            int r = lin >> 3, seg = lin & 7;
            float4 val = *(const float4*)&g_y[r * YSTRIDE + k0 + seg * 4];
            *(float4*)&ys[r][seg * 4] = val;
        }
        // W tile: ws[col][k] = W[cg*32+col][k0+k]; guard k >= SIGCH (pad -> 0).
#pragma unroll
        for (int ii = 0; ii < 4; ii++) {
            int lin = tid + 256 * ii;        // 0..1023
            int col = lin >> 5, k = lin & 31;
            int kg = k0 + k;
            ws[col][k] = (kg < SIGCH) ? W[(cg * 32 + col) * SIGCH + kg] : 0.0f;
        }
        __syncthreads();
#pragma unroll
        for (int kk = 0; kk < 32; kk += 2) {
            u64 w0 = *(const u64*)&ws[4 * cp + 0][kk];
            u64 w1 = *(const u64*)&ws[4 * cp + 1][kk];
            u64 w2 = *(const u64*)&ws[4 * cp + 2][kk];
            u64 w3 = *(const u64*)&ws[4 * cp + 3][kk];
            u64 y0 = *(const u64*)&ys[rg][kk];
            u64 y1 = *(const u64*)&ys[rg + 32][kk];
            u64 y2 = *(const u64*)&ys[rg + 64][kk];
            u64 y3 = *(const u64*)&ys[rg + 96][kk];
            acc2[0][0] = fma2(y0, w0, acc2[0][0]);
            acc2[0][1] = fma2(y0, w1, acc2[0][1]);
            acc2[0][2] = fma2(y0, w2, acc2[0][2]);
            acc2[0][3] = fma2(y0, w3, acc2[0][3]);
            acc2[1][0] = fma2(y1, w0, acc2[1][0]);
            acc2[1][1] = fma2(y1, w1, acc2[1][1]);
            acc2[1][2] = fma2(y1, w2, acc2[1][2]);
            acc2[1][3] = fma2(y1, w3, acc2[1][3]);
            acc2[2][0] = fma2(y2, w0, acc2[2][0]);
            acc2[2][1] = fma2(y2, w1, acc2[2][1]);
            acc2[2][2] = fma2(y2, w2, acc2[2][2]);
            acc2[2][3] = fma2(y2, w3, acc2[2][3]);
            acc2[3][0] = fma2(y3, w0, acc2[3][0]);
            acc2[3][1] = fma2(y3, w1, acc2[3][1]);
            acc2[3][2] = fma2(y3, w2, acc2[3][2]);
            acc2[3][3] = fma2(y3, w3, acc2[3][3]);
        }
        __syncthreads();
    }

    const int col0 = cg * 32 + 4 * cp;
    float* p = g_part + (size_t)sp * NB * DOUT;
#pragma unroll
    for (int i = 0; i < 4; i++) {
        float2 f0 = unpack2(acc2[i][0]);
        float2 f1 = unpack2(acc2[i][1]);
        float2 f2 = unpack2(acc2[i][2]);
        float2 f3 = unpack2(acc2[i][3]);
        float4 v = make_float4(f0.x + f0.y, f1.x + f1.y, f2.x + f2.y, f3.x + f3.y);
        *(float4*)&p[(rg + 32 * i) * DOUT + col0] = v;
    }
}

// ---------------------------------------------------------------------------
__global__ void reduce_bias_kernel(const float* __restrict__ bias, float* __restrict__ out)
{
    int idx = blockIdx.x * 256 + threadIdx.x;
    float v = bias[idx & (DOUT - 1)];
#pragma unroll
    for (int s = 0; s < KSPLIT; s++)
        v += g_part[s * NB * DOUT + idx];
    out[idx] = v;
}

// ---------------------------------------------------------------------------
extern "C" void kernel_launch(void* const* d_in, const int* in_sizes, int n_in,
                              void* d_out, int out_size)
{
    (void)in_sizes; (void)n_in; (void)out_size;
    const float* inp  = (const float*)d_in[0];   // (128,1024,7)
    const float* W    = (const float*)d_in[1];   // (256,4680)
    const float* bias = (const float*)d_in[2];   // (256,)
    float* out = (float*)d_out;                  // (128,256)

    const int smem_bytes = SMEM_FLOATS * sizeof(float);   // 149760
    cudaFuncSetAttribute(sig_scan_kernel,
                         cudaFuncAttributeMaxDynamicSharedMemorySize, smem_bytes);

    sig_scan_kernel<<<NB, 512, smem_bytes>>>(inp);
    dim3 g2(8, KSPLIT);
    gemm_part_kernel<<<g2, 256>>>(W);
    reduce_bias_kernel<<<NB, 256>>>(bias, out);
}

// round 12
// speedup vs baseline: 1.2068x; 1.2068x over previous
#include <cuda_runtime.h>

// SigNet: depth-4 path signature (C=8 incl. time) + linear head.
// R10-exact (measured 59.4us):
// K1: 8-way segmented scalar Chen scan (factored updates) + in-smem tree
//     combine. No f32x2, no peeling, no dynamic register-array indexing.
// K2: split-k GEMM, 296-CTA balanced wave (8 cg x KSPLIT 37), 16 scalar
//     accums/thread, transposed W tile.
// K3: reduce + bias.

#define NB      128
#define SLEN    1024
#define NSEG    8
#define SEG     128
#define CIN     7
#define SIGCH   4680          // 8 + 64 + 512 + 4096
#define YSTRIDE 4736          // 37*128; pad [4680,4736) stays zero
#define DOUT    256
#define KSPLIT  37
#define KCHUNK  128           // 37*128 = 4736

__device__ float g_y[NB * YSTRIDE];
__device__ float g_part[KSPLIT * NB * DOUT];

// smem: vs[1024][8] = 8192 floats, then reused as T[8][4680] = 37440 floats.
#define SMEM_FLOATS (NSEG * SIGCH)     // 37440 floats = 149760 B

// ---- Chen combine pieces (X = A o B, A earlier in time) ----
__device__ __forceinline__ void chen_l4(const float* __restrict__ A,
                                        const float* __restrict__ B,
                                        float* __restrict__ X, int lane, int nth)
{
    for (int e = lane; e < 4096; e += nth) {
        float v = A[584 + e] + B[584 + e];
        v = fmaf(A[e >> 9],        B[72 + (e & 511)], v);
        v = fmaf(A[8 + (e >> 6)],  B[8  + (e & 63)],  v);
        v = fmaf(A[72 + (e >> 3)], B[e & 7],          v);
        X[584 + e] = v;
    }
}
__device__ __forceinline__ void chen_l3(const float* __restrict__ A,
                                        const float* __restrict__ B,
                                        float* __restrict__ X, int lane, int nth)
{
    for (int e = lane; e < 512; e += nth) {
        float v = A[72 + e] + B[72 + e];
        v = fmaf(A[e >> 6],       B[8 + (e & 63)], v);
        v = fmaf(A[8 + (e >> 3)], B[e & 7],        v);
        X[72 + e] = v;
    }
}
__device__ __forceinline__ void chen_inplace(float* __restrict__ A,
                                             const float* __restrict__ B,
                                             int lane, int nth)
{
    chen_l4(A, B, A, lane, nth);      // reads A[0..584), writes A[584..)
    __syncthreads();
    chen_l3(A, B, A, lane, nth);      // reads A[0..72), writes A[72..584)
    float v2 = 0.0f, v1 = 0.0f;
    if (lane < 64) v2 = A[8 + lane] + B[8 + lane] + A[lane >> 3] * B[lane & 7];
    if (lane < 8)  v1 = A[lane] + B[lane];
    __syncthreads();
    if (lane < 64) A[8 + lane] = v2;
    if (lane < 8)  A[lane] = v1;
}

// ---------------------------------------------------------------------------
// Kernel 1: segmented scan. 1 CTA/batch, 512 threads = 8 groups x 64.
// Thread u=tid&63 owns (a,b)=(u>>3,u&7): all 8 c, all 8 d (64 L4 accumulators).
// ---------------------------------------------------------------------------
__global__ __launch_bounds__(512, 1) void sig_scan_kernel(const float* __restrict__ inp)
{
    extern __shared__ float sm[];
    const int b   = blockIdx.x;
    const int tid = threadIdx.x;

    // Build increments into sm[0..8192). Basepoint 0: first inc = first sample.
    const float dt = 1.0f / 1023.0f;
    const float* x = inp + (size_t)b * SLEN * CIN;
    for (int i = tid; i < SLEN * CIN; i += 512) {
        int t = i / CIN, c = i - t * CIN;
        float cur  = x[i];
        float prev = (t == 0) ? 0.0f : x[i - CIN];
        sm[t * 8 + c + 1] = cur - prev;
    }
    for (int t = tid; t < SLEN; t += 512)
        sm[t * 8] = (t == 0) ? 0.0f : dt;
    __syncthreads();

    const int g  = tid >> 6;          // segment 0..7
    const int u  = tid & 63;          // (a,b)
    const int a  = u >> 3;
    const int bb = u & 7;

    float s1 = 0.0f, s2 = 0.0f;
    float s3[8];
    float sig4[64];
#pragma unroll
    for (int i = 0; i < 8; i++) s3[i] = 0.0f;
#pragma unroll
    for (int i = 0; i < 64; i++) sig4[i] = 0.0f;

    const float inv24 = 1.0f / 24.0f;
    const float inv6  = 1.0f / 6.0f;
    const float* vrow = sm + g * SEG * 8;

#pragma unroll 1
    for (int t = 0; t < SEG; t++) {
        float vv[8];
        *(float4*)&vv[0] = *(const float4*)&vrow[t * 8];
        *(float4*)&vv[4] = *(const float4*)&vrow[t * 8 + 4];
        // Runtime-offset reads come from SHARED (LDS), never from the register
        // array: vv[a] would force vv into local memory.
        float va = vrow[t * 8 + a];
        float vb = vrow[t * 8 + bb];

        // All derived from OLD s1,s2,s3.
        float t6 = fmaf(s1, inv6, va * inv24);   // va/24 + s1/6
        float uu = fmaf(s1, 0.5f, va * inv6);    // va/6  + s1/2
        float m1 = fmaf(vb, t6, s2 * 0.5f);      // vb*t6 + s2/2
        float m2 = fmaf(vb, uu, s2);             // vb*uu + s2

        float K[8];
#pragma unroll
        for (int c = 0; c < 8; c++) {
            K[c]  = fmaf(vv[c], m1, s3[c]);
            s3[c] = fmaf(vv[c], m2, s3[c]);
        }
#pragma unroll
        for (int c = 0; c < 8; c++)
#pragma unroll
            for (int d = 0; d < 8; d++)
                sig4[c * 8 + d] = fmaf(K[c], vv[d], sig4[c * 8 + d]);

        s2 = fmaf(vb, fmaf(va, 0.5f, s1), s2);   // s2 + va*vb/2 + s1*vb
        s1 += va;
    }

    // All scan reads of sm done -> safe to overwrite with T[8][4680].
    __syncthreads();

    // Fully unrolled write-out: every sig4 index is a compile-time constant.
    float* P = sm + g * SIGCH;
#pragma unroll
    for (int c = 0; c < 8; c++) {
#pragma unroll
        for (int d = 0; d < 8; d++)
            P[584 + u * 64 + c * 8 + d] = sig4[c * 8 + d];
        P[72 + u * 8 + c] = s3[c];
    }
    P[8 + u] = s2;
    if (bb == 0) P[a] = s1;
    __syncthreads();

    // Round 1: 4 parallel in-place combines, 128 threads each.
    {
        int pair = tid >> 7, lane = tid & 127;
        float* A = sm + (2 * pair) * SIGCH;
        const float* B = A + SIGCH;
        chen_inplace(A, B, lane, 128);
    }
    __syncthreads();
    // Round 2: 2 parallel in-place combines, 256 threads each.
    {
        int pair = tid >> 8, lane = tid & 255;
        float* A = sm + (4 * pair) * SIGCH;
        const float* B = A + 2 * SIGCH;
        chen_inplace(A, B, lane, 256);
    }
    __syncthreads();
    // Round 3: final combine straight to global.
    {
        const float* A = sm;
        const float* B = sm + 4 * SIGCH;
        float* y = g_y + (size_t)b * YSTRIDE;
        chen_l4(A, B, y, tid, 512);
        chen_l3(A, B, y, tid, 512);
        if (tid < 64) y[8 + tid] = A[8 + tid] + B[8 + tid] + A[tid >> 3] * B[tid & 7];
        if (tid < 8)  y[tid] = A[tid] + B[tid];
        if (tid < YSTRIDE - SIGCH) y[SIGCH + tid] = 0.0f;   // 56 pad elems
    }
}

// ---------------------------------------------------------------------------
// Kernel 2: split-k GEMM partials. grid = (8 col-groups, KSPLIT=37) = 296 CTAs
// = exactly 2 resident CTAs on each of 148 SMs (one balanced wave).
// CTA: 128 batch-rows x 32 out-cols over 128 of k. 256 threads, 16 accums.
// ws stored transposed [k][col]; 36-float pitch keeps reads conflict-free.
// ---------------------------------------------------------------------------
__global__ __launch_bounds__(256, 2) void gemm_part_kernel(const float* __restrict__ W)
{
    __shared__ float ys[128][36];
    __shared__ float ws[32][36];    // [k][col]

    const int tid = threadIdx.x;
    const int cg = blockIdx.x;      // cols cg*32 .. cg*32+31
    const int sp = blockIdx.y;      // k in [sp*128, sp*128+128)
    const int kbase = sp * KCHUNK;

    const int cp = tid & 7;         // cols 4cp .. 4cp+3
    const int rg = tid >> 3;        // rows rg + 32*j, j<4

    float acc[4][4];
#pragma unroll
    for (int i = 0; i < 4; i++)
#pragma unroll
        for (int j = 0; j < 4; j++) acc[i][j] = 0.0f;

    for (int kc = 0; kc < KCHUNK; kc += 32) {
        const int k0 = kbase + kc;
        // y tile: 128 x 32
#pragma unroll
        for (int ii = 0; ii < 4; ii++) {
            int lin = tid + 256 * ii;
            int r = lin >> 3, seg = lin & 7;
            float4 val = *(const float4*)&g_y[r * YSTRIDE + k0 + seg * 4];
            *(float4*)&ys[r][seg * 4] = val;
        }
        // W tile transposed: ws[k][col] = W[cg*32+col][k0+k]; guard k >= SIGCH.
#pragma unroll
        for (int ii = 0; ii < 4; ii++) {
            int lin = tid + 256 * ii;        // 0..1023
            int col = lin >> 5, k = lin & 31;
            int kg = k0 + k;
            ws[k][col] = (kg < SIGCH) ? W[(cg * 32 + col) * SIGCH + kg] : 0.0f;
        }
        __syncthreads();
#pragma unroll
        for (int kk = 0; kk < 32; kk += 2) {
            float4 wA = *(const float4*)&ws[kk][4 * cp];
            float4 wB = *(const float4*)&ws[kk + 1][4 * cp];
            float2 y0 = *(const float2*)&ys[rg][kk];
            float2 y1 = *(const float2*)&ys[rg + 32][kk];
            float2 y2 = *(const float2*)&ys[rg + 64][kk];
            float2 y3 = *(const float2*)&ys[rg + 96][kk];
            acc[0][0] = fmaf(y0.x, wA.x, acc[0][0]); acc[0][0] = fmaf(y0.y, wB.x, acc[0][0]);
            acc[0][1] = fmaf(y0.x, wA.y, acc[0][1]); acc[0][1] = fmaf(y0.y, wB.y, acc[0][1]);
            acc[0][2] = fmaf(y0.x, wA.z, acc[0][2]); acc[0][2] = fmaf(y0.y, wB.z, acc[0][2]);
            acc[0][3] = fmaf(y0.x, wA.w, acc[0][3]); acc[0][3] = fmaf(y0.y, wB.w, acc[0][3]);
            acc[1][0] = fmaf(y1.x, wA.x, acc[1][0]); acc[1][0] = fmaf(y1.y, wB.x, acc[1][0]);
            acc[1][1] = fmaf(y1.x, wA.y, acc[1][1]); acc[1][1] = fmaf(y1.y, wB.y, acc[1][1]);
            acc[1][2] = fmaf(y1.x, wA.z, acc[1][2]); acc[1][2] = fmaf(y1.y, wB.z, acc[1][2]);
            acc[1][3] = fmaf(y1.x, wA.w, acc[1][3]); acc[1][3] = fmaf(y1.y, wB.w, acc[1][3]);
            acc[2][0] = fmaf(y2.x, wA.x, acc[2][0]); acc[2][0] = fmaf(y2.y, wB.x, acc[2][0]);
            acc[2][1] = fmaf(y2.x, wA.y, acc[2][1]); acc[2][1] = fmaf(y2.y, wB.y, acc[2][1]);
            acc[2][2] = fmaf(y2.x, wA.z, acc[2][2]); acc[2][2] = fmaf(y2.y, wB.z, acc[2][2]);
            acc[2][3] = fmaf(y2.x, wA.w, acc[2][3]); acc[2][3] = fmaf(y2.y, wB.w, acc[2][3]);
            acc[3][0] = fmaf(y3.x, wA.x, acc[3][0]); acc[3][0] = fmaf(y3.y, wB.x, acc[3][0]);
            acc[3][1] = fmaf(y3.x, wA.y, acc[3][1]); acc[3][1] = fmaf(y3.y, wB.y, acc[3][1]);
            acc[3][2] = fmaf(y3.x, wA.z, acc[3][2]); acc[3][2] = fmaf(y3.y, wB.z, acc[3][2]);
            acc[3][3] = fmaf(y3.x, wA.w, acc[3][3]); acc[3][3] = fmaf(y3.y, wB.w, acc[3][3]);
        }
        __syncthreads();
    }

    const int col0 = cg * 32 + 4 * cp;
    float* p = g_part + (size_t)sp * NB * DOUT;
#pragma unroll
    for (int i = 0; i < 4; i++) {
        float4 v = make_float4(acc[i][0], acc[i][1], acc[i][2], acc[i][3]);
        *(float4*)&p[(rg + 32 * i) * DOUT + col0] = v;
    }
}

// ---------------------------------------------------------------------------
__global__ void reduce_bias_kernel(const float* __restrict__ bias, float* __restrict__ out)
{
    int idx = blockIdx.x * 256 + threadIdx.x;
    float v = bias[idx & (DOUT - 1)];
#pragma unroll
    for (int s = 0; s < KSPLIT; s++)
        v += g_part[s * NB * DOUT + idx];
    out[idx] = v;
}

// ---------------------------------------------------------------------------
extern "C" void kernel_launch(void* const* d_in, const int* in_sizes, int n_in,
                              void* d_out, int out_size)
{
    (void)in_sizes; (void)n_in; (void)out_size;
    const float* inp  = (const float*)d_in[0];   // (128,1024,7)
    const float* W    = (const float*)d_in[1];   // (256,4680)
    const float* bias = (const float*)d_in[2];   // (256,)
    float* out = (float*)d_out;                  // (128,256)

    const int smem_bytes = SMEM_FLOATS * sizeof(float);   // 149760
    cudaFuncSetAttribute(sig_scan_kernel,
                         cudaFuncAttributeMaxDynamicSharedMemorySize, smem_bytes);

    sig_scan_kernel<<<NB, 512, smem_bytes>>>(inp);
    dim3 g2(8, KSPLIT);
    gemm_part_kernel<<<g2, 256>>>(W);
    reduce_bias_kernel<<<NB, 256>>>(bias, out);
}